// round 10
// baseline (speedup 1.0000x reference)
#include <cuda_runtime.h>
#include <cstdint>

// image [B=4, C=1, D=128, H=256, W=256] fp32
// out   [B, 2, D, H, W]: ch0 = copy, ch1 = sqrt(Gx^2+Gy^2+Gz^2 + 1e-8)
#define DIM_D 128
#define DIM_H 256
#define DIM_W 256
#define PLANE (DIM_H * DIM_W)
#define DCHUNK 64
#define KITER (DCHUNK / 2)          // plane pairs per chunk
#define NROWS 6                     // rows h0-1 .. h0+4 staged per plane
#define STAGE_F (NROWS * DIM_W)     // 1536 floats = 6 KB per buffer

__device__ __forceinline__ void cp16(uint32_t saddr, const float* gp) {
    asm volatile("cp.async.ca.shared.global [%0], [%1], 16;" :: "r"(saddr), "l"(gp));
}
__device__ __forceinline__ void cp_commit() { asm volatile("cp.async.commit_group;"); }
__device__ __forceinline__ void cp_wait1()  { asm volatile("cp.async.wait_group 1;" ::: "memory"); }

// Fold one staged plane (smem) into separable partials for this thread's row:
//   A = s_h*s_w(x) (Gz=d_d(A)); B = s_h*d_w(x) (Gx=s_d(B)); C = d_h*s_w(x) (Gy=s_d(C))
__device__ __forceinline__ void fold_smem(
    const float* __restrict__ sB,   // &sbuf[s][ty*DIM_W + w0]
    bool wl, bool wr,
    float4& A, float4& B, float4& C, float4* cen)
{
    A = make_float4(0.f, 0.f, 0.f, 0.f);
    B = A; C = A;
#pragma unroll
    for (int r = 0; r < 3; r++) {
        const float* row = sB + r * DIM_W;
        const float4 c = *reinterpret_cast<const float4*>(row);
        const float xl = wl ? row[-1] : 0.f;
        const float xr = wr ? row[4]  : 0.f;
        if (r == 1 && cen) *cen = c;

        float4 u, v;
        u.x = fmaf(2.f, c.x, xl  + c.y);
        u.y = fmaf(2.f, c.y, c.x + c.z);
        u.z = fmaf(2.f, c.z, c.y + c.w);
        u.w = fmaf(2.f, c.w, c.z + xr);
        v.x = c.y - xl;
        v.y = c.z - c.x;
        v.z = c.w - c.y;
        v.w = xr  - c.z;

        if (r == 1) {
            A.x = fmaf(2.f, u.x, A.x); A.y = fmaf(2.f, u.y, A.y);
            A.z = fmaf(2.f, u.z, A.z); A.w = fmaf(2.f, u.w, A.w);
            B.x = fmaf(2.f, v.x, B.x); B.y = fmaf(2.f, v.y, B.y);
            B.z = fmaf(2.f, v.z, B.z); B.w = fmaf(2.f, v.w, B.w);
        } else {
            const float dh = (r == 0) ? -1.f : 1.f;
            A.x += u.x; A.y += u.y; A.z += u.z; A.w += u.w;
            B.x += v.x; B.y += v.y; B.z += v.z; B.w += v.w;
            C.x = fmaf(dh, u.x, C.x); C.y = fmaf(dh, u.y, C.y);
            C.z = fmaf(dh, u.z, C.z); C.w = fmaf(dh, u.w, C.w);
        }
    }
}

__global__ void __launch_bounds__(256, 4)
sobel_edge_kernel(const float* __restrict__ img, float* __restrict__ out)
{
    __shared__ float sbuf[6][STAGE_F];   // 3 rotating PAIRS of plane buffers

    const int tx  = threadIdx.x;           // 0..63 -> w (float4)
    const int ty  = threadIdx.y;           // 0..3  -> h row
    const int tid = tx + ty * 64;          // 0..255
    const int w0  = tx * 4;
    const int h0  = blockIdx.x * 4;
    const int h   = h0 + ty;
    const int d0  = blockIdx.y * DCHUNK;
    const int b   = blockIdx.z;

    const bool wl = w0 > 0, wr = (w0 + 4) < DIM_W;

    const float* gbase = img + (size_t)b * (DIM_D * PLANE);

    // --- staging assignment: 384 16B chunks (6 rows x 64 float4) per plane ---
    const int r0 = tid >> 6,          c0 = tid & 63;
    const int r1 = (tid + 256) >> 6,  c1 = (tid + 256) & 63;
    const bool has1 = (tid + 256) < NROWS * 64;
    const int g0 = h0 - 1 + r0;
    const int g1 = h0 - 1 + r1;
    const bool gv0 = (g0 >= 0) && (g0 < DIM_H);
    const bool gv1 = (g1 >= 0) && (g1 < DIM_H);
    const float* gr0 = gbase + (size_t)g0 * DIM_W + c0 * 4;   // + p*PLANE at use
    const float* gr1 = gbase + (size_t)g1 * DIM_W + c1 * 4;
    const uint32_t sB0 = (uint32_t)__cvta_generic_to_shared(&sbuf[0][0]);
    const uint32_t so0 = (uint32_t)(r0 * DIM_W + c0 * 4) * 4u;
    const uint32_t so1 = (uint32_t)(r1 * DIM_W + c1 * 4) * 4u;
    float* z0 = &sbuf[0][r0 * DIM_W + c0 * 4];  // generic ptrs for zero-fill
    float* z1 = &sbuf[0][r1 * DIM_W + c1 * 4];

    const float4 f4z = make_float4(0.f, 0.f, 0.f, 0.f);

    // Stage plane p into buffer s (zero-fills invalid plane/rows). NO commit.
    auto stage_plane = [&](int s, int p) {
        const bool pv = (p >= 0) && (p < DIM_D);
        const size_t poff = (size_t)p * PLANE;
        const uint32_t sbase = sB0 + (uint32_t)s * (STAGE_F * 4u);
        if (pv && gv0) cp16(sbase + so0, gr0 + poff);
        else *reinterpret_cast<float4*>(z0 + s * STAGE_F) = f4z;
        if (has1) {
            if (pv && gv1) cp16(sbase + so1, gr1 + poff);
            else *reinterpret_cast<float4*>(z1 + s * STAGE_F) = f4z;
        }
    };

    // Output pointers
    float* o0 = out + (size_t)b * 2 * (DIM_D * PLANE)
              + (size_t)d0 * PLANE + (size_t)h * DIM_W + w0;   // copy ch, plane d0
    float* o1 = o0 + (size_t)(DIM_D * PLANE);                  // mag ch, plane d0
    const float* sMy = &sbuf[0][ty * DIM_W + w0];              // fold window, buf0

    float4 A0, B0, C0, A1, B1, C1, A2, B2, C2, cen;

    // --- prologue ---
    // pair0 (bufs 0,1): planes d0-1, d0 ; pair1 (bufs 2,3): planes d0+1, d0+2
    stage_plane(0, d0 - 1);
    stage_plane(1, d0);
    cp_commit();
    stage_plane(2, d0 + 1);
    stage_plane(3, d0 + 2);
    cp_commit();
    cp_wait1();                       // pair0 complete
    __syncthreads();
    fold_smem(sMy, wl, wr, A1, B1, C1, nullptr);                  // plane d0-1
    fold_smem(sMy + STAGE_F, wl, wr, A2, B2, C2, &cen);           // plane d0
    __stcs(reinterpret_cast<float4*>(o0), cen);                   // copy(d0)
    o0 += PLANE;                                                  // -> plane d0+1

    int sw = 2;   // pair to WRITE this iter (pair index 0..2)
    int sr = 1;   // pair to FOLD this iter

#pragma unroll 3
    for (int k = 0; k < KITER; k++) {
        // (1) stage planes d0+2k+3, d0+2k+4 into pair sw (skip on last iter)
        if (k < KITER - 1) {
            stage_plane(2 * sw,     d0 + 2 * k + 3);
            stage_plane(2 * sw + 1, d0 + 2 * k + 4);
        }
        cp_commit();

        // (2) wait for pair sr (planes d0+2k+1, d0+2k+2), one barrier
        cp_wait1();
        __syncthreads();
        const float* sP = &sbuf[2 * sr][ty * DIM_W + w0];

        // ---- plane d0+2k+1: rotate, fold (+copy), mag(d0+2k) ----
        A0 = A1; B0 = B1; C0 = C1;
        A1 = A2; B1 = B2; C1 = C2;
        fold_smem(sP, wl, wr, A2, B2, C2, &cen);
        __stcs(reinterpret_cast<float4*>(o0), cen);   // copy(d0+2k+1), always < d0+DCHUNK
        o0 += PLANE;
        {
            float4 gx, gy, gz, m;
            gx.x = fmaf(2.f, B1.x, B0.x + B2.x);
            gx.y = fmaf(2.f, B1.y, B0.y + B2.y);
            gx.z = fmaf(2.f, B1.z, B0.z + B2.z);
            gx.w = fmaf(2.f, B1.w, B0.w + B2.w);
            gy.x = fmaf(2.f, C1.x, C0.x + C2.x);
            gy.y = fmaf(2.f, C1.y, C0.y + C2.y);
            gy.z = fmaf(2.f, C1.z, C0.z + C2.z);
            gy.w = fmaf(2.f, C1.w, C0.w + C2.w);
            gz.x = A2.x - A0.x;
            gz.y = A2.y - A0.y;
            gz.z = A2.z - A0.z;
            gz.w = A2.w - A0.w;
            m.x = sqrtf(fmaf(gx.x, gx.x, fmaf(gy.x, gy.x, fmaf(gz.x, gz.x, 1e-8f))));
            m.y = sqrtf(fmaf(gx.y, gx.y, fmaf(gy.y, gy.y, fmaf(gz.y, gz.y, 1e-8f))));
            m.z = sqrtf(fmaf(gx.z, gx.z, fmaf(gy.z, gy.z, fmaf(gz.z, gz.z, 1e-8f))));
            m.w = sqrtf(fmaf(gx.w, gx.w, fmaf(gy.w, gy.w, fmaf(gz.w, gz.w, 1e-8f))));
            __stcs(reinterpret_cast<float4*>(o1), m); // mag(d0+2k)
            o1 += PLANE;
        }

        // ---- plane d0+2k+2: rotate, fold (+copy if chunk-owned), mag(d0+2k+1) ----
        A0 = A1; B0 = B1; C0 = C1;
        A1 = A2; B1 = B2; C1 = C2;
        fold_smem(sP + STAGE_F, wl, wr, A2, B2, C2, &cen);
        if (k < KITER - 1) {                          // plane d0+2k+2 < d0+DCHUNK
            __stcs(reinterpret_cast<float4*>(o0), cen);
        }
        o0 += PLANE;
        {
            float4 gx, gy, gz, m;
            gx.x = fmaf(2.f, B1.x, B0.x + B2.x);
            gx.y = fmaf(2.f, B1.y, B0.y + B2.y);
            gx.z = fmaf(2.f, B1.z, B0.z + B2.z);
            gx.w = fmaf(2.f, B1.w, B0.w + B2.w);
            gy.x = fmaf(2.f, C1.x, C0.x + C2.x);
            gy.y = fmaf(2.f, C1.y, C0.y + C2.y);
            gy.z = fmaf(2.f, C1.z, C0.z + C2.z);
            gy.w = fmaf(2.f, C1.w, C0.w + C2.w);
            gz.x = A2.x - A0.x;
            gz.y = A2.y - A0.y;
            gz.z = A2.z - A0.z;
            gz.w = A2.w - A0.w;
            m.x = sqrtf(fmaf(gx.x, gx.x, fmaf(gy.x, gy.x, fmaf(gz.x, gz.x, 1e-8f))));
            m.y = sqrtf(fmaf(gx.y, gx.y, fmaf(gy.y, gy.y, fmaf(gz.y, gz.y, 1e-8f))));
            m.z = sqrtf(fmaf(gx.z, gx.z, fmaf(gy.z, gy.z, fmaf(gz.z, gz.z, 1e-8f))));
            m.w = sqrtf(fmaf(gx.w, gx.w, fmaf(gy.w, gy.w, fmaf(gz.w, gz.w, 1e-8f))));
            __stcs(reinterpret_cast<float4*>(o1), m); // mag(d0+2k+1)
            o1 += PLANE;
        }

        // advance pair ring (constant after unroll-3 copy propagation)
        sw = (sw == 2) ? 0 : sw + 1;
        sr = (sr == 2) ? 0 : sr + 1;
    }
}

extern "C" void kernel_launch(void* const* d_in, const int* in_sizes, int n_in,
                              void* d_out, int out_size)
{
    const float* img = (const float*)d_in[0];
    float* out = (float*)d_out;

    dim3 block(64, 4, 1);                        // 256 threads
    dim3 grid(DIM_H / 4, DIM_D / DCHUNK, 4);     // 64 x 2 x 4 = 512 CTAs

    sobel_edge_kernel<<<grid, block>>>(img, out);
}

// round 11
// speedup vs baseline: 1.0037x; 1.0037x over previous
#include <cuda_runtime.h>
#include <cstdint>

// image [B=4, C=1, D=128, H=256, W=256] fp32
// out   [B, 2, D, H, W]: ch0 = copy, ch1 = sqrt(Gx^2+Gy^2+Gz^2 + 1e-8)
#define DIM_D 128
#define DIM_H 256
#define DIM_W 256
#define PLANE (DIM_H * DIM_W)
#define DCHUNK 64
#define NROWS 6                     // rows h0-1 .. h0+4 staged per plane
#define STAGE_F (NROWS * DIM_W)     // 1536 floats = 6 KB per buffer

__device__ __forceinline__ void cp16(uint32_t saddr, const float* gp) {
    asm volatile("cp.async.ca.shared.global [%0], [%1], 16;" :: "r"(saddr), "l"(gp));
}
__device__ __forceinline__ void cp_commit() { asm volatile("cp.async.commit_group;"); }
__device__ __forceinline__ void cp_wait1()  { asm volatile("cp.async.wait_group 1;" ::: "memory"); }
__device__ __forceinline__ void cp_wait2()  { asm volatile("cp.async.wait_group 2;" ::: "memory"); }

// Single-instruction approximate sqrt (MUFU.SQRT), ~1 ulp: fine vs 1e-3 tol.
__device__ __forceinline__ float sqrt_fast(float x) {
    float r; asm("sqrt.approx.f32 %0, %1;" : "=f"(r) : "f"(x)); return r;
}

// Fold one staged plane (smem) into separable partials for this thread's row:
//   A = s_h*s_w(x) (Gz=d_d(A)); B = s_h*d_w(x) (Gx=s_d(B)); C = d_h*s_w(x) (Gy=s_d(C))
__device__ __forceinline__ void fold_smem(
    const float* __restrict__ sB,   // &sbuf[s][ty*DIM_W + w0]
    bool wl, bool wr,
    float4& A, float4& B, float4& C, float4* cen)
{
    A = make_float4(0.f, 0.f, 0.f, 0.f);
    B = A; C = A;
#pragma unroll
    for (int r = 0; r < 3; r++) {
        const float* row = sB + r * DIM_W;
        const float4 c = *reinterpret_cast<const float4*>(row);
        const float xl = wl ? row[-1] : 0.f;
        const float xr = wr ? row[4]  : 0.f;
        if (r == 1 && cen) *cen = c;

        float4 u, v;
        u.x = fmaf(2.f, c.x, xl  + c.y);
        u.y = fmaf(2.f, c.y, c.x + c.z);
        u.z = fmaf(2.f, c.z, c.y + c.w);
        u.w = fmaf(2.f, c.w, c.z + xr);
        v.x = c.y - xl;
        v.y = c.z - c.x;
        v.z = c.w - c.y;
        v.w = xr  - c.z;

        if (r == 1) {
            A.x = fmaf(2.f, u.x, A.x); A.y = fmaf(2.f, u.y, A.y);
            A.z = fmaf(2.f, u.z, A.z); A.w = fmaf(2.f, u.w, A.w);
            B.x = fmaf(2.f, v.x, B.x); B.y = fmaf(2.f, v.y, B.y);
            B.z = fmaf(2.f, v.z, B.z); B.w = fmaf(2.f, v.w, B.w);
        } else {
            const float dh = (r == 0) ? -1.f : 1.f;
            A.x += u.x; A.y += u.y; A.z += u.z; A.w += u.w;
            B.x += v.x; B.y += v.y; B.z += v.z; B.w += v.w;
            C.x = fmaf(dh, u.x, C.x); C.y = fmaf(dh, u.y, C.y);
            C.z = fmaf(dh, u.z, C.z); C.w = fmaf(dh, u.w, C.w);
        }
    }
}

__global__ void __launch_bounds__(256, 4)
sobel_edge_kernel(const float* __restrict__ img, float* __restrict__ out)
{
    __shared__ float sbuf[3][STAGE_F];

    const int tx  = threadIdx.x;           // 0..63 -> w (float4)
    const int ty  = threadIdx.y;           // 0..3  -> h row
    const int tid = tx + ty * 64;          // 0..255
    const int w0  = tx * 4;
    const int h0  = blockIdx.x * 4;
    const int h   = h0 + ty;
    const int d0  = blockIdx.y * DCHUNK;
    const int b   = blockIdx.z;

    const bool wl = w0 > 0, wr = (w0 + 4) < DIM_W;

    const float* gbase = img + (size_t)b * (DIM_D * PLANE);

    // --- staging assignment: 384 16B chunks (6 rows x 64 float4) per plane ---
    const int r0 = tid >> 6,          c0 = tid & 63;
    const int r1 = (tid + 256) >> 6,  c1 = (tid + 256) & 63;
    const bool has1 = (tid + 256) < NROWS * 64;
    const int g0 = h0 - 1 + r0;
    const int g1 = h0 - 1 + r1;
    const bool gv0 = (g0 >= 0) && (g0 < DIM_H);
    const bool gv1 = (g1 >= 0) && (g1 < DIM_H);
    const float* gr0 = gbase + (size_t)g0 * DIM_W + c0 * 4;   // + p*PLANE at use
    const float* gr1 = gbase + (size_t)g1 * DIM_W + c1 * 4;
    const uint32_t sB0 = (uint32_t)__cvta_generic_to_shared(&sbuf[0][0]);
    const uint32_t so0 = (uint32_t)(r0 * DIM_W + c0 * 4) * 4u;
    const uint32_t so1 = (uint32_t)(r1 * DIM_W + c1 * 4) * 4u;
    float* z0 = &sbuf[0][r0 * DIM_W + c0 * 4];  // generic ptrs for zero-fill
    float* z1 = &sbuf[0][r1 * DIM_W + c1 * 4];

    const float4 f4z = make_float4(0.f, 0.f, 0.f, 0.f);

    // Stage plane p into buffer s (zero-fills invalid plane/rows). Always commits.
    auto stage = [&](int s, int p, bool need) {
        if (need) {
            const bool pv = (p >= 0) && (p < DIM_D);
            const size_t poff = (size_t)p * PLANE;
            const uint32_t sbase = sB0 + (uint32_t)s * (STAGE_F * 4u);
            if (pv && gv0) cp16(sbase + so0, gr0 + poff);
            else *reinterpret_cast<float4*>(z0 + s * STAGE_F) = f4z;
            if (has1) {
                if (pv && gv1) cp16(sbase + so1, gr1 + poff);
                else *reinterpret_cast<float4*>(z1 + s * STAGE_F) = f4z;
            }
        }
        cp_commit();
    };

    // Output pointers
    float* o0 = out + (size_t)b * 2 * (DIM_D * PLANE)
              + (size_t)d0 * PLANE + (size_t)h * DIM_W + w0;   // copy ch, plane d0
    float* o1 = o0 + (size_t)(DIM_D * PLANE);                  // mag ch, plane d0
    const float* sMy = &sbuf[0][ty * DIM_W + w0];              // fold window, buf0

    float4 A0, B0, C0, A1, B1, C1, A2, B2, C2, cen;

    // --- prologue: stage planes d0-1, d0, d0+1 into bufs 0,1,2 ---
    stage(0, d0 - 1, true);
    stage(1, d0,     true);
    stage(2, d0 + 1, true);
    cp_wait2();
    __syncthreads();
    fold_smem(sMy, wl, wr, A1, B1, C1, nullptr);                  // plane d0-1
    cp_wait1();
    __syncthreads();
    fold_smem(sMy + STAGE_F, wl, wr, A2, B2, C2, &cen);           // plane d0
    __stcs(reinterpret_cast<float4*>(o0), cen);                   // copy(d0)
    o0 += PLANE;                                                  // -> plane d0+1

    int sw = 0;   // write buffer for this iter
    int sr = 2;   // read (fold) buffer for this iter

#pragma unroll 3
    for (int dd = 0; dd < DCHUNK; dd++) {
        // (1) stage plane d0+dd+2 into buf sw (not needed on last iter)
        stage(sw, d0 + dd + 2, dd < DCHUNK - 1);

        // (2) wait for plane d0+dd+1 (committed 2 groups ago), sync, fold it
        cp_wait1();
        __syncthreads();
        A0 = A1; B0 = B1; C0 = C1;
        A1 = A2; B1 = B2; C1 = C2;
        fold_smem(&sbuf[sr][ty * DIM_W + w0], wl, wr, A2, B2, C2, &cen);
        if (dd < DCHUNK - 1) {                    // copy(d0+dd+1) owned by this chunk
            __stcs(reinterpret_cast<float4*>(o0), cen);
        }
        o0 += PLANE;

        // (3) magnitude for plane d0+dd (approx sqrt: 1 MUFU per element)
        float4 gx, gy, gz, m;
        gx.x = fmaf(2.f, B1.x, B0.x + B2.x);
        gx.y = fmaf(2.f, B1.y, B0.y + B2.y);
        gx.z = fmaf(2.f, B1.z, B0.z + B2.z);
        gx.w = fmaf(2.f, B1.w, B0.w + B2.w);
        gy.x = fmaf(2.f, C1.x, C0.x + C2.x);
        gy.y = fmaf(2.f, C1.y, C0.y + C2.y);
        gy.z = fmaf(2.f, C1.z, C0.z + C2.z);
        gy.w = fmaf(2.f, C1.w, C0.w + C2.w);
        gz.x = A2.x - A0.x;
        gz.y = A2.y - A0.y;
        gz.z = A2.z - A0.z;
        gz.w = A2.w - A0.w;
        m.x = sqrt_fast(fmaf(gx.x, gx.x, fmaf(gy.x, gy.x, fmaf(gz.x, gz.x, 1e-8f))));
        m.y = sqrt_fast(fmaf(gx.y, gx.y, fmaf(gy.y, gy.y, fmaf(gz.y, gz.y, 1e-8f))));
        m.z = sqrt_fast(fmaf(gx.z, gx.z, fmaf(gy.z, gy.z, fmaf(gz.z, gz.z, 1e-8f))));
        m.w = sqrt_fast(fmaf(gx.w, gx.w, fmaf(gy.w, gy.w, fmaf(gz.w, gz.w, 1e-8f))));

        __stcs(reinterpret_cast<float4*>(o1), m);
        o1 += PLANE;

        // advance buffer ring (constant after unroll-3 copy propagation)
        sw = (sw == 2) ? 0 : sw + 1;
        sr = (sr == 2) ? 0 : sr + 1;
    }
}

extern "C" void kernel_launch(void* const* d_in, const int* in_sizes, int n_in,
                              void* d_out, int out_size)
{
    const float* img = (const float*)d_in[0];
    float* out = (float*)d_out;

    dim3 block(64, 4, 1);                        // 256 threads
    dim3 grid(DIM_H / 4, DIM_D / DCHUNK, 4);     // 64 x 2 x 4 = 512 CTAs

    sobel_edge_kernel<<<grid, block>>>(img, out);
}

// round 12
// speedup vs baseline: 1.0639x; 1.0600x over previous
#include <cuda_runtime.h>
#include <cstdint>

// image [B=4, C=1, D=128, H=256, W=256] fp32
// out   [B, 2, D, H, W]: ch0 = copy, ch1 = sqrt(Gx^2+Gy^2+Gz^2 + 1e-8)
#define DIM_D 128
#define DIM_H 256
#define DIM_W 256
#define PLANE (DIM_H * DIM_W)
#define DCHUNK 64
#define NROWS 4                     // rows h0-1 .. h0+2 staged per plane
#define STAGE_F (NROWS * DIM_W)     // 1024 floats = 4 KB per buffer

__device__ __forceinline__ void cp16(uint32_t saddr, const float* gp) {
    asm volatile("cp.async.ca.shared.global [%0], [%1], 16;" :: "r"(saddr), "l"(gp));
}
__device__ __forceinline__ void cp_commit() { asm volatile("cp.async.commit_group;"); }
__device__ __forceinline__ void cp_wait1()  { asm volatile("cp.async.wait_group 1;" ::: "memory"); }
__device__ __forceinline__ void cp_wait2()  { asm volatile("cp.async.wait_group 2;" ::: "memory"); }

// Single-instruction approximate sqrt (MUFU.SQRT), ~1 ulp: fine vs 1e-3 tol.
__device__ __forceinline__ float sqrt_fast(float x) {
    float r; asm("sqrt.approx.f32 %0, %1;" : "=f"(r) : "f"(x)); return r;
}

// Fold one staged plane (smem) into separable partials for this thread's row:
//   A = s_h*s_w(x) (Gz=d_d(A)); B = s_h*d_w(x) (Gx=s_d(B)); C = d_h*s_w(x) (Gy=s_d(C))
__device__ __forceinline__ void fold_smem(
    const float* __restrict__ sB,   // &sbuf[s][ty*DIM_W + w0]
    bool wl, bool wr,
    float4& A, float4& B, float4& C, float4* cen)
{
    A = make_float4(0.f, 0.f, 0.f, 0.f);
    B = A; C = A;
#pragma unroll
    for (int r = 0; r < 3; r++) {
        const float* row = sB + r * DIM_W;
        const float4 c = *reinterpret_cast<const float4*>(row);
        const float xl = wl ? row[-1] : 0.f;
        const float xr = wr ? row[4]  : 0.f;
        if (r == 1 && cen) *cen = c;

        float4 u, v;
        u.x = fmaf(2.f, c.x, xl  + c.y);
        u.y = fmaf(2.f, c.y, c.x + c.z);
        u.z = fmaf(2.f, c.z, c.y + c.w);
        u.w = fmaf(2.f, c.w, c.z + xr);
        v.x = c.y - xl;
        v.y = c.z - c.x;
        v.z = c.w - c.y;
        v.w = xr  - c.z;

        if (r == 1) {
            A.x = fmaf(2.f, u.x, A.x); A.y = fmaf(2.f, u.y, A.y);
            A.z = fmaf(2.f, u.z, A.z); A.w = fmaf(2.f, u.w, A.w);
            B.x = fmaf(2.f, v.x, B.x); B.y = fmaf(2.f, v.y, B.y);
            B.z = fmaf(2.f, v.z, B.z); B.w = fmaf(2.f, v.w, B.w);
        } else {
            const float dh = (r == 0) ? -1.f : 1.f;
            A.x += u.x; A.y += u.y; A.z += u.z; A.w += u.w;
            B.x += v.x; B.y += v.y; B.z += v.z; B.w += v.w;
            C.x = fmaf(dh, u.x, C.x); C.y = fmaf(dh, u.y, C.y);
            C.z = fmaf(dh, u.z, C.z); C.w = fmaf(dh, u.w, C.w);
        }
    }
}

__global__ void __launch_bounds__(128, 8)
sobel_edge_kernel(const float* __restrict__ img, float* __restrict__ out)
{
    __shared__ float sbuf[3][STAGE_F];   // 12 KB

    const int tx  = threadIdx.x;           // 0..63 -> w (float4)
    const int ty  = threadIdx.y;           // 0..1  -> h row
    const int tid = tx + ty * 64;           // 0..127
    const int w0  = tx * 4;
    const int h0  = blockIdx.x * 2;
    const int h   = h0 + ty;
    const int d0  = blockIdx.y * DCHUNK;
    const int b   = blockIdx.z;

    const bool wl = w0 > 0, wr = (w0 + 4) < DIM_W;

    const float* gbase = img + (size_t)b * (DIM_D * PLANE);

    // staging: 256 16B chunks (4 rows x 64 float4) per plane, 128 threads x 2
    const int r0 = tid >> 6,          c0 = tid & 63;          // rows 0,1
    const int r1 = (tid + 128) >> 6,  c1 = (tid + 128) & 63;  // rows 2,3
    const int g0 = h0 - 1 + r0;
    const int g1 = h0 - 1 + r1;
    const bool gv0 = (g0 >= 0) && (g0 < DIM_H);
    const bool gv1 = (g1 >= 0) && (g1 < DIM_H);
    const float* gr0 = gbase + (size_t)g0 * DIM_W + c0 * 4;   // + p*PLANE at use
    const float* gr1 = gbase + (size_t)g1 * DIM_W + c1 * 4;
    const uint32_t sB0 = (uint32_t)__cvta_generic_to_shared(&sbuf[0][0]);
    const uint32_t so0 = (uint32_t)(r0 * DIM_W + c0 * 4) * 4u;
    const uint32_t so1 = (uint32_t)(r1 * DIM_W + c1 * 4) * 4u;
    float* z0 = &sbuf[0][r0 * DIM_W + c0 * 4];  // generic ptrs for zero-fill
    float* z1 = &sbuf[0][r1 * DIM_W + c1 * 4];

    const float4 f4z = make_float4(0.f, 0.f, 0.f, 0.f);

    // Stage plane p into buffer s (zero-fills invalid plane/rows). Always commits.
    auto stage = [&](int s, int p, bool need) {
        if (need) {
            const bool pv = (p >= 0) && (p < DIM_D);
            const size_t poff = (size_t)p * PLANE;
            const uint32_t sbase = sB0 + (uint32_t)s * (STAGE_F * 4u);
            if (pv && gv0) cp16(sbase + so0, gr0 + poff);
            else *reinterpret_cast<float4*>(z0 + s * STAGE_F) = f4z;
            if (pv && gv1) cp16(sbase + so1, gr1 + poff);
            else *reinterpret_cast<float4*>(z1 + s * STAGE_F) = f4z;
        }
        cp_commit();
    };

    // Output pointers
    float* o0 = out + (size_t)b * 2 * (DIM_D * PLANE)
              + (size_t)d0 * PLANE + (size_t)h * DIM_W + w0;   // copy ch, plane d0
    float* o1 = o0 + (size_t)(DIM_D * PLANE);                  // mag ch, plane d0
    const float* sMy = &sbuf[0][ty * DIM_W + w0];              // fold window, buf0

    float4 A0, B0, C0, A1, B1, C1, A2, B2, C2, cen;

    // --- prologue: stage planes d0-1, d0, d0+1 into bufs 0,1,2 ---
    stage(0, d0 - 1, true);
    stage(1, d0,     true);
    stage(2, d0 + 1, true);
    cp_wait2();
    __syncthreads();
    fold_smem(sMy, wl, wr, A1, B1, C1, nullptr);                  // plane d0-1
    cp_wait1();
    __syncthreads();
    fold_smem(sMy + STAGE_F, wl, wr, A2, B2, C2, &cen);           // plane d0
    __stcs(reinterpret_cast<float4*>(o0), cen);                   // copy(d0)
    o0 += PLANE;                                                  // -> plane d0+1

    int sw = 0;   // write buffer for this iter
    int sr = 2;   // read (fold) buffer for this iter

#pragma unroll 3
    for (int dd = 0; dd < DCHUNK; dd++) {
        // (1) stage plane d0+dd+2 into buf sw (not needed on last iter)
        stage(sw, d0 + dd + 2, dd < DCHUNK - 1);

        // (2) wait for plane d0+dd+1 (committed 2 groups ago), sync, fold it
        cp_wait1();
        __syncthreads();
        A0 = A1; B0 = B1; C0 = C1;
        A1 = A2; B1 = B2; C1 = C2;
        fold_smem(&sbuf[sr][ty * DIM_W + w0], wl, wr, A2, B2, C2, &cen);
        if (dd < DCHUNK - 1) {                    // copy(d0+dd+1) owned by this chunk
            __stcs(reinterpret_cast<float4*>(o0), cen);
        }
        o0 += PLANE;

        // (3) magnitude for plane d0+dd (approx sqrt: 1 MUFU per element)
        float4 gx, gy, gz, m;
        gx.x = fmaf(2.f, B1.x, B0.x + B2.x);
        gx.y = fmaf(2.f, B1.y, B0.y + B2.y);
        gx.z = fmaf(2.f, B1.z, B0.z + B2.z);
        gx.w = fmaf(2.f, B1.w, B0.w + B2.w);
        gy.x = fmaf(2.f, C1.x, C0.x + C2.x);
        gy.y = fmaf(2.f, C1.y, C0.y + C2.y);
        gy.z = fmaf(2.f, C1.z, C0.z + C2.z);
        gy.w = fmaf(2.f, C1.w, C0.w + C2.w);
        gz.x = A2.x - A0.x;
        gz.y = A2.y - A0.y;
        gz.z = A2.z - A0.z;
        gz.w = A2.w - A0.w;
        m.x = sqrt_fast(fmaf(gx.x, gx.x, fmaf(gy.x, gy.x, fmaf(gz.x, gz.x, 1e-8f))));
        m.y = sqrt_fast(fmaf(gx.y, gx.y, fmaf(gy.y, gy.y, fmaf(gz.y, gz.y, 1e-8f))));
        m.z = sqrt_fast(fmaf(gx.z, gx.z, fmaf(gy.z, gy.z, fmaf(gz.z, gz.z, 1e-8f))));
        m.w = sqrt_fast(fmaf(gx.w, gx.w, fmaf(gy.w, gy.w, fmaf(gz.w, gz.w, 1e-8f))));

        __stcs(reinterpret_cast<float4*>(o1), m);
        o1 += PLANE;

        // advance buffer ring (constant after unroll-3 copy propagation)
        sw = (sw == 2) ? 0 : sw + 1;
        sr = (sr == 2) ? 0 : sr + 1;
    }
}

extern "C" void kernel_launch(void* const* d_in, const int* in_sizes, int n_in,
                              void* d_out, int out_size)
{
    const float* img = (const float*)d_in[0];
    float* out = (float*)d_out;

    dim3 block(64, 2, 1);                        // 128 threads
    dim3 grid(DIM_H / 2, DIM_D / DCHUNK, 4);     // 128 x 2 x 4 = 1024 CTAs (1 wave @8/SM)

    sobel_edge_kernel<<<grid, block>>>(img, out);
}

// round 13
// speedup vs baseline: 1.1756x; 1.1049x over previous
#include <cuda_runtime.h>
#include <cstdint>

// image [B=4, C=1, D=128, H=256, W=256] fp32
// out   [B, 2, D, H, W]: ch0 = copy, ch1 = sqrt(Gx^2+Gy^2+Gz^2 + 1e-8)
#define DIM_D 128
#define DIM_H 256
#define DIM_W 256
#define PLANE (DIM_H * DIM_W)
#define DCHUNK 64
#define NROWS 4                     // rows h0-1 .. h0+2 staged per plane
#define STAGE_F (NROWS * DIM_W)     // 1024 floats = 4 KB per buffer

__device__ __forceinline__ void cp16(uint32_t saddr, const float* gp) {
    asm volatile("cp.async.ca.shared.global [%0], [%1], 16;" :: "r"(saddr), "l"(gp));
}
__device__ __forceinline__ void cp_commit() { asm volatile("cp.async.commit_group;"); }
__device__ __forceinline__ void cp_wait1()  { asm volatile("cp.async.wait_group 1;" ::: "memory"); }
__device__ __forceinline__ void cp_wait2()  { asm volatile("cp.async.wait_group 2;" ::: "memory"); }

// Single-instruction approximate sqrt (MUFU.SQRT), ~1 ulp: fine vs 1e-3 tol.
__device__ __forceinline__ float sqrt_fast(float x) {
    float r; asm("sqrt.approx.f32 %0, %1;" : "=f"(r) : "f"(x)); return r;
}

// Fold one staged plane (smem) into separable partials for this thread's row.
// Halo values come from warp shuffles; only warp-boundary lanes touch smem
// (single-lane predicated LDS.32 = 1 wavefront, vs 4-way-conflicted full-warp
// LDS.32 before).
//   A = s_h*s_w(x) (Gz=d_d(A)); B = s_h*d_w(x) (Gx=s_d(B)); C = d_h*s_w(x) (Gy=s_d(C))
__device__ __forceinline__ void fold_smem(
    const float* __restrict__ sB,   // &sbuf[s][ty*DIM_W + w0]
    int lane, bool edge_l, bool edge_r,   // edge_*: this warp's boundary lane is at the image edge
    float4& A, float4& B, float4& C, float4* cen)
{
    A = make_float4(0.f, 0.f, 0.f, 0.f);
    B = A; C = A;
#pragma unroll
    for (int r = 0; r < 3; r++) {
        const float* row = sB + r * DIM_W;
        const float4 c = *reinterpret_cast<const float4*>(row);

        // halo exchange: interior lanes from neighbors, boundary lane from smem
        float xl = __shfl_up_sync(0xffffffffu, c.w, 1);
        if (lane == 0)  xl = edge_l ? 0.f : row[-1];
        float xr = __shfl_down_sync(0xffffffffu, c.x, 1);
        if (lane == 31) xr = edge_r ? 0.f : row[4];

        if (r == 1 && cen) *cen = c;

        float4 u, v;
        u.x = fmaf(2.f, c.x, xl  + c.y);
        u.y = fmaf(2.f, c.y, c.x + c.z);
        u.z = fmaf(2.f, c.z, c.y + c.w);
        u.w = fmaf(2.f, c.w, c.z + xr);
        v.x = c.y - xl;
        v.y = c.z - c.x;
        v.z = c.w - c.y;
        v.w = xr  - c.z;

        if (r == 1) {
            A.x = fmaf(2.f, u.x, A.x); A.y = fmaf(2.f, u.y, A.y);
            A.z = fmaf(2.f, u.z, A.z); A.w = fmaf(2.f, u.w, A.w);
            B.x = fmaf(2.f, v.x, B.x); B.y = fmaf(2.f, v.y, B.y);
            B.z = fmaf(2.f, v.z, B.z); B.w = fmaf(2.f, v.w, B.w);
        } else {
            const float dh = (r == 0) ? -1.f : 1.f;
            A.x += u.x; A.y += u.y; A.z += u.z; A.w += u.w;
            B.x += v.x; B.y += v.y; B.z += v.z; B.w += v.w;
            C.x = fmaf(dh, u.x, C.x); C.y = fmaf(dh, u.y, C.y);
            C.z = fmaf(dh, u.z, C.z); C.w = fmaf(dh, u.w, C.w);
        }
    }
}

__global__ void __launch_bounds__(128, 8)
sobel_edge_kernel(const float* __restrict__ img, float* __restrict__ out)
{
    __shared__ float sbuf[3][STAGE_F];   // 12 KB

    const int tx  = threadIdx.x;           // 0..63 -> w (float4)
    const int ty  = threadIdx.y;           // 0..1  -> h row
    const int tid = tx + ty * 64;           // 0..127
    const int lane = tx & 31;
    const int w0  = tx * 4;
    const int h0  = blockIdx.x * 2;
    const int h   = h0 + ty;
    const int d0  = blockIdx.y * DCHUNK;
    const int b   = blockIdx.z;

    // This warp covers tx [0..31] or [32..63]; its boundary lanes are at the
    // image edge only for tx==0 (left) / tx==63 (right).
    const bool edge_l = (tx & 32) == 0;    // warp's lane0 has w0 == 0
    const bool edge_r = (tx & 32) != 0;    // warp's lane31 has w0 == 252

    const float* gbase = img + (size_t)b * (DIM_D * PLANE);

    // staging: 256 16B chunks (4 rows x 64 float4) per plane, 128 threads x 2
    const int r0 = tid >> 6,          c0 = tid & 63;          // rows 0,1
    const int r1 = (tid + 128) >> 6,  c1 = (tid + 128) & 63;  // rows 2,3
    const int g0 = h0 - 1 + r0;
    const int g1 = h0 - 1 + r1;
    const bool gv0 = (g0 >= 0) && (g0 < DIM_H);
    const bool gv1 = (g1 >= 0) && (g1 < DIM_H);
    const float* gr0 = gbase + (size_t)g0 * DIM_W + c0 * 4;   // + p*PLANE at use
    const float* gr1 = gbase + (size_t)g1 * DIM_W + c1 * 4;
    const uint32_t sB0 = (uint32_t)__cvta_generic_to_shared(&sbuf[0][0]);
    const uint32_t so0 = (uint32_t)(r0 * DIM_W + c0 * 4) * 4u;
    const uint32_t so1 = (uint32_t)(r1 * DIM_W + c1 * 4) * 4u;
    float* z0 = &sbuf[0][r0 * DIM_W + c0 * 4];  // generic ptrs for zero-fill
    float* z1 = &sbuf[0][r1 * DIM_W + c1 * 4];

    const float4 f4z = make_float4(0.f, 0.f, 0.f, 0.f);

    // Stage plane p into buffer s (zero-fills invalid plane/rows). Always commits.
    auto stage = [&](int s, int p, bool need) {
        if (need) {
            const bool pv = (p >= 0) && (p < DIM_D);
            const size_t poff = (size_t)p * PLANE;
            const uint32_t sbase = sB0 + (uint32_t)s * (STAGE_F * 4u);
            if (pv && gv0) cp16(sbase + so0, gr0 + poff);
            else *reinterpret_cast<float4*>(z0 + s * STAGE_F) = f4z;
            if (pv && gv1) cp16(sbase + so1, gr1 + poff);
            else *reinterpret_cast<float4*>(z1 + s * STAGE_F) = f4z;
        }
        cp_commit();
    };

    // Output pointers
    float* o0 = out + (size_t)b * 2 * (DIM_D * PLANE)
              + (size_t)d0 * PLANE + (size_t)h * DIM_W + w0;   // copy ch, plane d0
    float* o1 = o0 + (size_t)(DIM_D * PLANE);                  // mag ch, plane d0
    const float* sMy = &sbuf[0][ty * DIM_W + w0];              // fold window, buf0

    float4 A0, B0, C0, A1, B1, C1, A2, B2, C2, cen;

    // --- prologue: stage planes d0-1, d0, d0+1 into bufs 0,1,2 ---
    stage(0, d0 - 1, true);
    stage(1, d0,     true);
    stage(2, d0 + 1, true);
    cp_wait2();
    __syncthreads();
    fold_smem(sMy, lane, edge_l, edge_r, A1, B1, C1, nullptr);            // d0-1
    cp_wait1();
    __syncthreads();
    fold_smem(sMy + STAGE_F, lane, edge_l, edge_r, A2, B2, C2, &cen);     // d0
    __stcs(reinterpret_cast<float4*>(o0), cen);                           // copy(d0)
    o0 += PLANE;                                                          // -> d0+1

    int sw = 0;   // write buffer for this iter
    int sr = 2;   // read (fold) buffer for this iter

#pragma unroll 3
    for (int dd = 0; dd < DCHUNK; dd++) {
        // (1) stage plane d0+dd+2 into buf sw (not needed on last iter)
        stage(sw, d0 + dd + 2, dd < DCHUNK - 1);

        // (2) wait for plane d0+dd+1 (committed 2 groups ago), sync, fold it
        cp_wait1();
        __syncthreads();
        A0 = A1; B0 = B1; C0 = C1;
        A1 = A2; B1 = B2; C1 = C2;
        fold_smem(&sbuf[sr][ty * DIM_W + w0], lane, edge_l, edge_r, A2, B2, C2, &cen);
        if (dd < DCHUNK - 1) {                    // copy(d0+dd+1) owned by this chunk
            __stcs(reinterpret_cast<float4*>(o0), cen);
        }
        o0 += PLANE;

        // (3) magnitude for plane d0+dd (approx sqrt: 1 MUFU per element)
        float4 gx, gy, gz, m;
        gx.x = fmaf(2.f, B1.x, B0.x + B2.x);
        gx.y = fmaf(2.f, B1.y, B0.y + B2.y);
        gx.z = fmaf(2.f, B1.z, B0.z + B2.z);
        gx.w = fmaf(2.f, B1.w, B0.w + B2.w);
        gy.x = fmaf(2.f, C1.x, C0.x + C2.x);
        gy.y = fmaf(2.f, C1.y, C0.y + C2.y);
        gy.z = fmaf(2.f, C1.z, C0.z + C2.z);
        gy.w = fmaf(2.f, C1.w, C0.w + C2.w);
        gz.x = A2.x - A0.x;
        gz.y = A2.y - A0.y;
        gz.z = A2.z - A0.z;
        gz.w = A2.w - A0.w;
        m.x = sqrt_fast(fmaf(gx.x, gx.x, fmaf(gy.x, gy.x, fmaf(gz.x, gz.x, 1e-8f))));
        m.y = sqrt_fast(fmaf(gx.y, gx.y, fmaf(gy.y, gy.y, fmaf(gz.y, gz.y, 1e-8f))));
        m.z = sqrt_fast(fmaf(gx.z, gx.z, fmaf(gy.z, gy.z, fmaf(gz.z, gz.z, 1e-8f))));
        m.w = sqrt_fast(fmaf(gx.w, gx.w, fmaf(gy.w, gy.w, fmaf(gz.w, gz.w, 1e-8f))));

        __stcs(reinterpret_cast<float4*>(o1), m);
        o1 += PLANE;

        // advance buffer ring (constant after unroll-3 copy propagation)
        sw = (sw == 2) ? 0 : sw + 1;
        sr = (sr == 2) ? 0 : sr + 1;
    }
}

extern "C" void kernel_launch(void* const* d_in, const int* in_sizes, int n_in,
                              void* d_out, int out_size)
{
    const float* img = (const float*)d_in[0];
    float* out = (float*)d_out;

    dim3 block(64, 2, 1);                        // 128 threads
    dim3 grid(DIM_H / 2, DIM_D / DCHUNK, 4);     // 128 x 2 x 4 = 1024 CTAs (1 wave @8/SM)

    sobel_edge_kernel<<<grid, block>>>(img, out);
}